// round 2
// baseline (speedup 1.0000x reference)
#include <cuda_runtime.h>

// Problem constants (from reference setup_inputs)
#define B_   256
#define J_   17
#define HW_  6912            // 96*72
#define V4_  (HW_ / 4)       // 1728 float4 per (b,j) slice
#define BJ_  (B_ * J_)       // 4352

// Scratch: transposed partials, g_partials[j * B_ + b]
__device__ float        g_partials[BJ_];
__device__ unsigned int g_done = 0;   // reset to 0 by last block each run

__global__ __launch_bounds__(256) void jmse_fused_kernel(
    const float* __restrict__ out,
    const float* __restrict__ tgt,
    const float* __restrict__ wgt,
    const int*  __restrict__ topk_ptr,
    float*      __restrict__ result)
{
    const int bj = blockIdx.x;          // bj = b*J_ + j (input layout order)
    const size_t base = (size_t)bj * HW_;
    const float4* __restrict__ o4 = (const float4*)(out + base);
    const float4* __restrict__ t4 = (const float4*)(tgt + base);

    float acc = 0.0f;
    #pragma unroll 4
    for (int i = threadIdx.x; i < V4_; i += 256) {
        float4 a = o4[i];
        float4 b = t4[i];
        float d0 = a.x - b.x;
        float d1 = a.y - b.y;
        float d2 = a.z - b.z;
        float d3 = a.w - b.w;
        acc = fmaf(d0, d0, acc);
        acc = fmaf(d1, d1, acc);
        acc = fmaf(d2, d2, acc);
        acc = fmaf(d3, d3, acc);
    }

    // block reduce
    #pragma unroll
    for (int off = 16; off > 0; off >>= 1)
        acc += __shfl_xor_sync(0xFFFFFFFFu, acc, off);

    __shared__ float warp_sums[8];
    const int lane = threadIdx.x & 31;
    const int wid  = threadIdx.x >> 5;
    if (lane == 0) warp_sums[wid] = acc;
    __syncthreads();

    __shared__ bool is_last;
    if (wid == 0) {
        float s = (lane < 8) ? warp_sums[lane] : 0.0f;
        #pragma unroll
        for (int off = 4; off > 0; off >>= 1)
            s += __shfl_xor_sync(0xFFFFFFFFu, s, off);
        if (lane == 0) {
            const float w = wgt[bj];                 // [B, J, 1] contiguous
            const int b = bj / J_;
            const int j = bj - b * J_;
            g_partials[j * B_ + b] = s * w * w;      // transposed store
            __threadfence();                         // publish before counting
            unsigned int prev = atomicAdd(&g_done, 1u);
            is_last = (prev == (unsigned)(BJ_ - 1));
        }
    }
    __syncthreads();

    if (!is_last) return;

    // ---- last block: final reduction + top-k (all 8 warps participate) ----
    __shared__ float losses[J_];
    for (int j = wid; j < J_; j += 8) {
        // 256 contiguous partials per joint; 8 per lane
        float s = 0.0f;
        const float* p = &g_partials[j * B_];
        #pragma unroll
        for (int b = lane; b < B_; b += 32)
            s += __ldcg(p + b);                      // bypass (stale) L1
        #pragma unroll
        for (int off = 16; off > 0; off >>= 1)
            s += __shfl_xor_sync(0xFFFFFFFFu, s, off);
        if (lane == 0)
            losses[j] = s * (1.0f / ((float)B_ * (float)HW_));
    }
    __syncthreads();

    if (threadIdx.x == 0) {
        const int k = *topk_ptr;
        float v[J_];
        #pragma unroll
        for (int j = 0; j < J_; j++) v[j] = losses[j];
        float sum = 0.0f;
        for (int s = 0; s < k; s++) {
            int   best_i = 0;
            float best_v = v[0];
            #pragma unroll
            for (int j = 1; j < J_; j++)
                if (v[j] > best_v) { best_v = v[j]; best_i = j; }
            sum += best_v;
            v[best_i] = -3.402823466e38f;
        }
        result[0] = sum / (float)k;
        g_done = 0;                                  // reset for next replay
    }
}

extern "C" void kernel_launch(void* const* d_in, const int* in_sizes, int n_in,
                              void* d_out, int out_size)
{
    const float* out_t = (const float*)d_in[0];
    const float* tgt_t = (const float*)d_in[1];
    const float* wgt_t = (const float*)d_in[2];
    const int*   topk  = (const int*)d_in[3];
    float* res = (float*)d_out;

    jmse_fused_kernel<<<BJ_, 256>>>(out_t, tgt_t, wgt_t, topk, res);
}

// round 3
// speedup vs baseline: 1.0420x; 1.0420x over previous
#include <cuda_runtime.h>

// Problem constants (from reference setup_inputs)
#define B_   256
#define J_   17
#define HW_  6912            // 96*72
#define V4_  (HW_ / 4)       // 1728 float4 per (b,j) slice
#define BJ_  (B_ * J_)       // 4352

// Scratch: transposed partials, g_partials[j * B_ + b] (contiguous per joint)
__device__ float g_partials[BJ_];

// ---------------------------------------------------------------------------
// Kernel A: one block per (b,j) slice. Streams 2x 27648 B, reduces to 1 float.
// ---------------------------------------------------------------------------
__global__ __launch_bounds__(256) void jmse_partial_kernel(
    const float* __restrict__ out,
    const float* __restrict__ tgt,
    const float* __restrict__ wgt)
{
    const int bj = blockIdx.x;
    const size_t base = (size_t)bj * HW_;
    const float4* __restrict__ o4 = (const float4*)(out + base);
    const float4* __restrict__ t4 = (const float4*)(tgt + base);

    float acc = 0.0f;
    #pragma unroll 4
    for (int i = threadIdx.x; i < V4_; i += 256) {
        float4 a = o4[i];
        float4 b = t4[i];
        float d0 = a.x - b.x;
        float d1 = a.y - b.y;
        float d2 = a.z - b.z;
        float d3 = a.w - b.w;
        acc = fmaf(d0, d0, acc);
        acc = fmaf(d1, d1, acc);
        acc = fmaf(d2, d2, acc);
        acc = fmaf(d3, d3, acc);
    }

    // warp reduce
    #pragma unroll
    for (int off = 16; off > 0; off >>= 1)
        acc += __shfl_xor_sync(0xFFFFFFFFu, acc, off);

    __shared__ float warp_sums[8];
    const int lane = threadIdx.x & 31;
    const int wid  = threadIdx.x >> 5;
    if (lane == 0) warp_sums[wid] = acc;
    __syncthreads();

    if (wid == 0) {
        float s = (lane < 8) ? warp_sums[lane] : 0.0f;
        #pragma unroll
        for (int off = 4; off > 0; off >>= 1)
            s += __shfl_xor_sync(0xFFFFFFFFu, s, off);
        if (lane == 0) {
            const float w = wgt[bj];                 // [B, J, 1] contiguous
            const int b = bj / J_;
            const int j = bj - b * J_;
            g_partials[j * B_ + b] = s * w * w;      // transposed store
        }
    }
    // Signal: dependent grid may begin launching. Memory visibility for the
    // consumer is provided by griddepcontrol.wait at full-grid completion.
    asm volatile("griddepcontrol.launch_dependents;");
}

// ---------------------------------------------------------------------------
// Kernel B (PDL secondary): 17 warps, one per joint; contiguous float4 loads.
// ---------------------------------------------------------------------------
__global__ __launch_bounds__(544) void jmse_final_kernel(
    const int* __restrict__ topk_ptr,
    float* __restrict__ result)
{
    // Block until primary grid (kernel A) completes and its writes are visible.
    asm volatile("griddepcontrol.wait;");

    __shared__ float losses[J_];
    const int wid  = threadIdx.x >> 5;   // 0..16
    const int lane = threadIdx.x & 31;

    if (wid < J_) {
        // 256 floats per joint = 64 float4, 2 per lane
        const float4* p4 = (const float4*)&g_partials[wid * B_];
        float4 a = p4[lane];
        float4 b = p4[lane + 32];
        float s = (a.x + a.y) + (a.z + a.w) + (b.x + b.y) + (b.z + b.w);
        #pragma unroll
        for (int off = 16; off > 0; off >>= 1)
            s += __shfl_xor_sync(0xFFFFFFFFu, s, off);
        if (lane == 0)
            losses[wid] = s * (1.0f / ((float)B_ * (float)HW_));
    }
    __syncthreads();

    if (threadIdx.x == 0) {
        const int k = *topk_ptr;
        float v[J_];
        #pragma unroll
        for (int j = 0; j < J_; j++) v[j] = losses[j];
        float sum = 0.0f;
        for (int s = 0; s < k; s++) {
            int   best_i = 0;
            float best_v = v[0];
            #pragma unroll
            for (int j = 1; j < J_; j++)
                if (v[j] > best_v) { best_v = v[j]; best_i = j; }
            sum += best_v;
            v[best_i] = -3.402823466e38f;
        }
        result[0] = sum / (float)k;
    }
}

// ---------------------------------------------------------------------------
extern "C" void kernel_launch(void* const* d_in, const int* in_sizes, int n_in,
                              void* d_out, int out_size)
{
    const float* out_t = (const float*)d_in[0];
    const float* tgt_t = (const float*)d_in[1];
    const float* wgt_t = (const float*)d_in[2];
    const int*   topk  = (const int*)d_in[3];
    float* res = (float*)d_out;

    jmse_partial_kernel<<<BJ_, 256>>>(out_t, tgt_t, wgt_t);

    // Secondary launch with programmatic dependent launch: its setup overlaps
    // kernel A's execution; griddepcontrol.wait gates the actual work.
    cudaLaunchConfig_t cfg = {};
    cfg.gridDim  = dim3(1, 1, 1);
    cfg.blockDim = dim3(544, 1, 1);
    cfg.dynamicSmemBytes = 0;
    cfg.stream = 0;
    cudaLaunchAttribute attr[1];
    attr[0].id = cudaLaunchAttributeProgrammaticStreamSerialization;
    attr[0].val.programmaticStreamSerializationAllowed = 1;
    cfg.attrs = attr;
    cfg.numAttrs = 1;
    cudaLaunchKernelEx(&cfg, jmse_final_kernel, topk, res);
}

// round 4
// speedup vs baseline: 1.0835x; 1.0399x over previous
#include <cuda_runtime.h>

// Problem constants (from reference setup_inputs)
#define B_   256
#define J_   17
#define HW_  6912            // 96*72
#define V4_  (HW_ / 4)       // 1728 float4 per (b,j) slice
#define BJ_  (B_ * J_)       // 4352

// Scratch: transposed partials, g_partials[j * B_ + b] (contiguous per joint)
__device__ float g_partials[BJ_];

// ---------------------------------------------------------------------------
// Kernel A: one block per (b,j) slice. Streams 2x 27648 B, reduces to 1 float.
// ---------------------------------------------------------------------------
__global__ __launch_bounds__(256) void jmse_partial_kernel(
    const float* __restrict__ out,
    const float* __restrict__ tgt,
    const float* __restrict__ wgt)
{
    // Fire the PDL trigger IMMEDIATELY: lets kernel B launch and park at its
    // griddepcontrol.wait while we stream. Visibility of our writes is
    // guaranteed by the wait (full primary completion + flush), not by this.
    asm volatile("griddepcontrol.launch_dependents;");

    const int bj = blockIdx.x;
    const size_t base = (size_t)bj * HW_;
    const float4* __restrict__ o4 = (const float4*)(out + base);
    const float4* __restrict__ t4 = (const float4*)(tgt + base);

    float acc = 0.0f;
    #pragma unroll 4
    for (int i = threadIdx.x; i < V4_; i += 256) {
        float4 a = o4[i];
        float4 b = t4[i];
        float d0 = a.x - b.x;
        float d1 = a.y - b.y;
        float d2 = a.z - b.z;
        float d3 = a.w - b.w;
        acc = fmaf(d0, d0, acc);
        acc = fmaf(d1, d1, acc);
        acc = fmaf(d2, d2, acc);
        acc = fmaf(d3, d3, acc);
    }

    // warp reduce
    #pragma unroll
    for (int off = 16; off > 0; off >>= 1)
        acc += __shfl_xor_sync(0xFFFFFFFFu, acc, off);

    __shared__ float warp_sums[8];
    const int lane = threadIdx.x & 31;
    const int wid  = threadIdx.x >> 5;
    if (lane == 0) warp_sums[wid] = acc;
    __syncthreads();

    if (wid == 0) {
        float s = (lane < 8) ? warp_sums[lane] : 0.0f;
        #pragma unroll
        for (int off = 4; off > 0; off >>= 1)
            s += __shfl_xor_sync(0xFFFFFFFFu, s, off);
        if (lane == 0) {
            const float w = wgt[bj];                 // [B, J, 1] contiguous
            const int b = bj / J_;
            const int j = bj - b * J_;
            g_partials[j * B_ + b] = s * w * w;      // transposed store
        }
    }
}

// ---------------------------------------------------------------------------
// Kernel B (PDL secondary): 17 warps, one per joint; contiguous float4 loads.
// Launches early (primary triggers at start), parks at wait until A finishes.
// ---------------------------------------------------------------------------
__global__ __launch_bounds__(544) void jmse_final_kernel(
    const int* __restrict__ topk_ptr,
    float* __restrict__ result)
{
    // Hoistable setup (no dependence on A's data) happens before the wait.
    __shared__ float losses[J_];
    const int wid  = threadIdx.x >> 5;   // 0..16
    const int lane = threadIdx.x & 31;

    // Block until primary grid (kernel A) completes and its writes are visible.
    asm volatile("griddepcontrol.wait;");

    if (wid < J_) {
        // 256 floats per joint = 64 float4, 2 per lane
        const float4* p4 = (const float4*)&g_partials[wid * B_];
        float4 a = p4[lane];
        float4 b = p4[lane + 32];
        float s = (a.x + a.y) + (a.z + a.w) + (b.x + b.y) + (b.z + b.w);
        #pragma unroll
        for (int off = 16; off > 0; off >>= 1)
            s += __shfl_xor_sync(0xFFFFFFFFu, s, off);
        if (lane == 0)
            losses[wid] = s * (1.0f / ((float)B_ * (float)HW_));
    }
    __syncthreads();

    if (threadIdx.x == 0) {
        const int k = *topk_ptr;
        float v[J_];
        #pragma unroll
        for (int j = 0; j < J_; j++) v[j] = losses[j];
        float sum = 0.0f;
        for (int s = 0; s < k; s++) {
            int   best_i = 0;
            float best_v = v[0];
            #pragma unroll
            for (int j = 1; j < J_; j++)
                if (v[j] > best_v) { best_v = v[j]; best_i = j; }
            sum += best_v;
            v[best_i] = -3.402823466e38f;
        }
        result[0] = sum / (float)k;
    }
}

// ---------------------------------------------------------------------------
extern "C" void kernel_launch(void* const* d_in, const int* in_sizes, int n_in,
                              void* d_out, int out_size)
{
    const float* out_t = (const float*)d_in[0];
    const float* tgt_t = (const float*)d_in[1];
    const float* wgt_t = (const float*)d_in[2];
    const int*   topk  = (const int*)d_in[3];
    float* res = (float*)d_out;

    jmse_partial_kernel<<<BJ_, 256>>>(out_t, tgt_t, wgt_t);

    // Secondary launch with programmatic dependent launch: launches as soon as
    // all primary CTAs have fired launch_dependents (i.e., right away), then
    // parks at griddepcontrol.wait until A completes.
    cudaLaunchConfig_t cfg = {};
    cfg.gridDim  = dim3(1, 1, 1);
    cfg.blockDim = dim3(544, 1, 1);
    cfg.dynamicSmemBytes = 0;
    cfg.stream = 0;
    cudaLaunchAttribute attr[1];
    attr[0].id = cudaLaunchAttributeProgrammaticStreamSerialization;
    attr[0].val.programmaticStreamSerializationAllowed = 1;
    cfg.attrs = attr;
    cfg.numAttrs = 1;
    cudaLaunchKernelEx(&cfg, jmse_final_kernel, topk, res);
}